// round 3
// baseline (speedup 1.0000x reference)
#include <cuda_runtime.h>
#include <cuda_bf16.h>
#include <math.h>

// Problem constants
#define BB 4
#define SS 512
#define DD 1024
#define HH 16
#define LL 6
#define FFD 4096
#define VV 32000
#define DKK 64
#define NTOK (BB*SS)          // 2048

// ---------------------------------------------------------------------------
// Scratch (device globals; no allocation allowed)
// ---------------------------------------------------------------------------
__device__ float g_x[NTOK*DD];
__device__ float g_h[NTOK*DD];
__device__ float g_q[NTOK*DD];
__device__ float g_k[NTOK*DD];
__device__ float g_v[NTOK*DD];
__device__ float g_o[NTOK*DD];
__device__ float g_att[(size_t)BB*HH*SS*SS];   // 64 MB
__device__ float g_ff[(size_t)NTOK*FFD];       // 32 MB

// ---------------------------------------------------------------------------
// Embedding + positional add (pe row indexed by BATCH index, per reference)
// ---------------------------------------------------------------------------
__global__ void embed_kernel(const int* __restrict__ ids,
                             const float* __restrict__ emb,
                             const float* __restrict__ pe,
                             float* __restrict__ x)
{
    int idx = blockIdx.x * blockDim.x + threadIdx.x;
    if (idx >= NTOK * DD) return;
    int row = idx / DD;
    int d   = idx - row * DD;
    int b   = row / SS;
    x[idx] = emb[(size_t)ids[row] * DD + d] + pe[b * DD + d];
}

// ---------------------------------------------------------------------------
// LayerNorm (two-pass; one block of 256 threads per row)
// ---------------------------------------------------------------------------
__global__ void ln_kernel(const float* __restrict__ x,
                          const float* __restrict__ s,
                          const float* __restrict__ bvec,
                          float* __restrict__ out)
{
    __shared__ float red[256];
    int row = blockIdx.x;
    const float* p = x + (size_t)row * DD;
    int t = threadIdx.x;

    float acc = 0.f;
    for (int d = t; d < DD; d += 256) acc += p[d];
    red[t] = acc; __syncthreads();
    for (int o = 128; o > 0; o >>= 1) { if (t < o) red[t] += red[t + o]; __syncthreads(); }
    float mean = red[0] / DD;
    __syncthreads();

    acc = 0.f;
    for (int d = t; d < DD; d += 256) { float v = p[d] - mean; acc += v * v; }
    red[t] = acc; __syncthreads();
    for (int o = 128; o > 0; o >>= 1) { if (t < o) red[t] += red[t + o]; __syncthreads(); }
    float rstd = rsqrtf(red[0] / DD + 1e-5f);

    float* q = out + (size_t)row * DD;
    for (int d = t; d < DD; d += 256)
        q[d] = (p[d] - mean) * rstd * s[d] + bvec[d];
}

// ---------------------------------------------------------------------------
// GEMM: C[M,N] = epilogue(A[M,K] @ B + bias) (+ residual)
//   TB=false: B is [K,N] row-major (NN);  TB=true: B is [N,K] row-major (NT)
//   OP: 0 = none, 1 = exact gelu, 2 = add residual
// Tiles: 128(M) x 128(N) x 16(K), 256 threads, 8x8 micro-tile, float4
// everywhere, register prefetch of the next k-tile.
// Requires M%128==0, N%128==0, K%16==0 (true for all uses here).
// ---------------------------------------------------------------------------
template <int OP, bool TB>
__global__ __launch_bounds__(256, 2)
void gemm_kernel(const float* __restrict__ A,
                 const float* __restrict__ B,
                 const float* __restrict__ bias,
                 const float* __restrict__ res,
                 float* __restrict__ C,
                 int M, int N, int K)
{
    __shared__ float As[16][132];
    __shared__ float Bs[16][132];

    int tid = threadIdx.x;
    int mTile = blockIdx.x * 128;
    int nTile = blockIdx.y * 128;

    int m0 = (tid >> 4) * 8;     // 0..120
    int n0 = (tid & 15) * 8;     // 0..120

    // A loader coords: 128 rows x 16 k = 512 float4; 2 per thread
    int ar  = tid >> 2;          // 0..63
    int ac4 = (tid & 3) * 4;     // 0,4,8,12
    const float* Abase = A + (size_t)(mTile + ar) * K + ac4;

    // B loader coords
    int bkNN  = tid >> 5;            // 0..7   (NN: k index)
    int bn4NN = (tid & 31) * 4;      // 0..124 (NN: n offset)
    int bnNT  = tid >> 2;            // 0..63  (NT: n index)
    int bk4NT = (tid & 3) * 4;       // 0,4,8,12
    const float* BbaseNN = B + (size_t)bkNN * N + nTile + bn4NN;
    const float* BbaseNT = B + (size_t)(nTile + bnNT) * K + bk4NT;

    float acc[8][8];
#pragma unroll
    for (int i = 0; i < 8; i++)
#pragma unroll
        for (int j = 0; j < 8; j++) acc[i][j] = 0.f;

    // prefetch first tile into registers
    float4 a0, a1, b0, b1;
    a0 = *(const float4*)(Abase);
    a1 = *(const float4*)(Abase + (size_t)64 * K);
    if (!TB) {
        b0 = *(const float4*)(BbaseNN);
        b1 = *(const float4*)(BbaseNN + (size_t)8 * N);
    } else {
        b0 = *(const float4*)(BbaseNT);
        b1 = *(const float4*)(BbaseNT + (size_t)64 * K);
    }

    for (int kt = 0; kt < K; kt += 16) {
        // store prefetched regs to smem
        As[ac4 + 0][ar] = a0.x; As[ac4 + 1][ar] = a0.y;
        As[ac4 + 2][ar] = a0.z; As[ac4 + 3][ar] = a0.w;
        As[ac4 + 0][ar + 64] = a1.x; As[ac4 + 1][ar + 64] = a1.y;
        As[ac4 + 2][ar + 64] = a1.z; As[ac4 + 3][ar + 64] = a1.w;
        if (!TB) {
            *(float4*)&Bs[bkNN][bn4NN]     = b0;
            *(float4*)&Bs[bkNN + 8][bn4NN] = b1;
        } else {
            Bs[bk4NT + 0][bnNT] = b0.x; Bs[bk4NT + 1][bnNT] = b0.y;
            Bs[bk4NT + 2][bnNT] = b0.z; Bs[bk4NT + 3][bnNT] = b0.w;
            Bs[bk4NT + 0][bnNT + 64] = b1.x; Bs[bk4NT + 1][bnNT + 64] = b1.y;
            Bs[bk4NT + 2][bnNT + 64] = b1.z; Bs[bk4NT + 3][bnNT + 64] = b1.w;
        }
        __syncthreads();

        // prefetch next tile
        if (kt + 16 < K) {
            const float* Ap = Abase + kt + 16;
            a0 = *(const float4*)(Ap);
            a1 = *(const float4*)(Ap + (size_t)64 * K);
            if (!TB) {
                const float* Bp = BbaseNN + (size_t)(kt + 16) * N;
                b0 = *(const float4*)(Bp);
                b1 = *(const float4*)(Bp + (size_t)8 * N);
            } else {
                const float* Bp = BbaseNT + kt + 16;
                b0 = *(const float4*)(Bp);
                b1 = *(const float4*)(Bp + (size_t)64 * K);
            }
        }

        // compute
#pragma unroll
        for (int kk = 0; kk < 16; kk++) {
            float4 av0 = *(const float4*)&As[kk][m0];
            float4 av1 = *(const float4*)&As[kk][m0 + 4];
            float4 bv0 = *(const float4*)&Bs[kk][n0];
            float4 bv1 = *(const float4*)&Bs[kk][n0 + 4];
            float a[8] = {av0.x, av0.y, av0.z, av0.w, av1.x, av1.y, av1.z, av1.w};
            float b[8] = {bv0.x, bv0.y, bv0.z, bv0.w, bv1.x, bv1.y, bv1.z, bv1.w};
#pragma unroll
            for (int i = 0; i < 8; i++)
#pragma unroll
                for (int j = 0; j < 8; j++) acc[i][j] = fmaf(a[i], b[j], acc[i][j]);
        }
        __syncthreads();
    }

    // epilogue
    float bb[8];
    if (bias) {
#pragma unroll
        for (int j = 0; j < 8; j++) bb[j] = bias[nTile + n0 + j];
    } else {
#pragma unroll
        for (int j = 0; j < 8; j++) bb[j] = 0.f;
    }

#pragma unroll
    for (int i = 0; i < 8; i++) {
        int gm = mTile + m0 + i;
        size_t ci = (size_t)gm * N + nTile + n0;
        float v[8];
#pragma unroll
        for (int j = 0; j < 8; j++) {
            float t = acc[i][j] + bb[j];
            if (OP == 1) t = 0.5f * t * (1.0f + erff(t * 0.70710678118654752f));
            v[j] = t;
        }
        if (OP == 2) {
            float4 r0 = *(const float4*)(res + ci);
            float4 r1 = *(const float4*)(res + ci + 4);
            v[0] += r0.x; v[1] += r0.y; v[2] += r0.z; v[3] += r0.w;
            v[4] += r1.x; v[5] += r1.y; v[6] += r1.z; v[7] += r1.w;
        }
        float4 o0 = {v[0], v[1], v[2], v[3]};
        float4 o1 = {v[4], v[5], v[6], v[7]};
        *(float4*)(C + ci)     = o0;
        *(float4*)(C + ci + 4) = o1;
    }
}

// ---------------------------------------------------------------------------
// Attention: scores = scale * Q Kt (causal), per (b,h). 64x64 tiles, DK=64.
// ---------------------------------------------------------------------------
__global__ void attn_scores_kernel(const float* __restrict__ q,
                                   const float* __restrict__ k,
                                   float* __restrict__ att,
                                   float scale)
{
    if (blockIdx.x > blockIdx.y) return;   // fully masked tile
    __shared__ float As[16][65];
    __shared__ float Bs[16][65];

    int bh = blockIdx.z;
    int b = bh / HH, h = bh % HH;
    int qi0 = blockIdx.y * 64, ki0 = blockIdx.x * 64;
    int tid = threadIdx.x;

    const float* qb = q + (size_t)b * SS * DD + h * DKK;
    const float* kb = k + (size_t)b * SS * DD + h * DKK;

    int m0 = (tid >> 4) * 4;
    int n0 = (tid & 15) * 4;

    float acc[4][4];
#pragma unroll
    for (int i = 0; i < 4; i++)
#pragma unroll
        for (int j = 0; j < 4; j++) acc[i][j] = 0.f;

    for (int kt = 0; kt < DKK; kt += 16) {
#pragma unroll
        for (int i = 0; i < 4; i++) {
            int e = tid + i * 256;
            int m = e >> 4, kk = e & 15;
            As[kk][m] = qb[(size_t)(qi0 + m) * DD + kt + kk];
            Bs[kk][m] = kb[(size_t)(ki0 + m) * DD + kt + kk];
        }
        __syncthreads();
#pragma unroll
        for (int kk = 0; kk < 16; kk++) {
            float a[4], bbv[4];
#pragma unroll
            for (int i = 0; i < 4; i++) a[i] = As[kk][m0 + i];
#pragma unroll
            for (int j = 0; j < 4; j++) bbv[j] = Bs[kk][n0 + j];
#pragma unroll
            for (int i = 0; i < 4; i++)
#pragma unroll
                for (int j = 0; j < 4; j++) acc[i][j] = fmaf(a[i], bbv[j], acc[i][j]);
        }
        __syncthreads();
    }

#pragma unroll
    for (int i = 0; i < 4; i++) {
        int qi = qi0 + m0 + i;
#pragma unroll
        for (int j = 0; j < 4; j++) {
            int ki = ki0 + n0 + j;
            float v = acc[i][j] * scale;
            if (ki > qi) v = -1e30f;
            att[((size_t)bh * SS + qi) * SS + ki] = v;
        }
    }
}

// ---------------------------------------------------------------------------
// Causal softmax over a row (length qi+1); zeros the masked tail.
// ---------------------------------------------------------------------------
__global__ void softmax_kernel(float* __restrict__ att)
{
    __shared__ float red[128];
    int r = blockIdx.x;
    int qi = r & (SS - 1);
    float* p = att + (size_t)r * SS;
    int len = qi + 1;
    int t = threadIdx.x;

    float mx = -1e30f;
    for (int i = t; i < len; i += 128) mx = fmaxf(mx, p[i]);
    red[t] = mx; __syncthreads();
    for (int o = 64; o > 0; o >>= 1) { if (t < o) red[t] = fmaxf(red[t], red[t + o]); __syncthreads(); }
    mx = red[0]; __syncthreads();

    float sm = 0.f;
    for (int i = t; i < len; i += 128) sm += expf(p[i] - mx);
    red[t] = sm; __syncthreads();
    for (int o = 64; o > 0; o >>= 1) { if (t < o) red[t] += red[t + o]; __syncthreads(); }
    float inv = 1.0f / red[0];

    for (int i = t; i < len; i += 128) p[i] = expf(p[i] - mx) * inv;
    for (int i = len + t; i < SS; i += 128) p[i] = 0.f;
}

// ---------------------------------------------------------------------------
// O = att @ V per (b,h). Tile 64(qi) x 64(d); K limited causally to the tile.
// ---------------------------------------------------------------------------
__global__ void attn_av_kernel(const float* __restrict__ att,
                               const float* __restrict__ v,
                               float* __restrict__ o)
{
    __shared__ float As[16][65];
    __shared__ float Bs[16][65];

    int bh = blockIdx.z;
    int b = bh / HH, h = bh % HH;
    int qi0 = blockIdx.x * 64;
    int tid = threadIdx.x;

    const float* ab = att + (size_t)bh * SS * SS;
    const float* vb = v + (size_t)b * SS * DD + h * DKK;

    int m0 = (tid >> 4) * 4;
    int n0 = (tid & 15) * 4;

    float acc[4][4];
#pragma unroll
    for (int i = 0; i < 4; i++)
#pragma unroll
        for (int j = 0; j < 4; j++) acc[i][j] = 0.f;

    int kmax = qi0 + 64;   // causal: rows in this tile never attend past qi0+63
    for (int kt = 0; kt < kmax; kt += 16) {
#pragma unroll
        for (int i = 0; i < 4; i++) {
            int e = tid + i * 256;
            { int m = e >> 4, kk = e & 15;
              As[kk][m] = ab[(size_t)(qi0 + m) * SS + kt + kk]; }
            { int kk = e >> 6, n = e & 63;
              Bs[kk][n] = vb[(size_t)(kt + kk) * DD + n]; }
        }
        __syncthreads();
#pragma unroll
        for (int kk = 0; kk < 16; kk++) {
            float a[4], bbv[4];
#pragma unroll
            for (int i = 0; i < 4; i++) a[i] = As[kk][m0 + i];
#pragma unroll
            for (int j = 0; j < 4; j++) bbv[j] = Bs[kk][n0 + j];
#pragma unroll
            for (int i = 0; i < 4; i++)
#pragma unroll
                for (int j = 0; j < 4; j++) acc[i][j] = fmaf(a[i], bbv[j], acc[i][j]);
        }
        __syncthreads();
    }

#pragma unroll
    for (int i = 0; i < 4; i++) {
        int qi = qi0 + m0 + i;
#pragma unroll
        for (int j = 0; j < 4; j++)
            o[((size_t)b * SS + qi) * DD + h * DKK + n0 + j] = acc[i][j];
    }
}

// ---------------------------------------------------------------------------
// Host launcher
// ---------------------------------------------------------------------------
extern "C" void kernel_launch(void* const* d_in, const int* in_sizes, int n_in,
                              void* d_out, int out_size)
{
    const int*   ids   = (const int*)  d_in[0];
    const float* emb   = (const float*)d_in[1];
    const float* pe    = (const float*)d_in[2];
    const float* Wq    = (const float*)d_in[3];
    const float* Wk    = (const float*)d_in[4];
    const float* Wv    = (const float*)d_in[5];
    const float* Wo    = (const float*)d_in[6];
    const float* bo    = (const float*)d_in[7];
    const float* ln1s  = (const float*)d_in[8];
    const float* ln1b  = (const float*)d_in[9];
    const float* ln2s  = (const float*)d_in[10];
    const float* ln2b  = (const float*)d_in[11];
    const float* W1    = (const float*)d_in[12];
    const float* b1    = (const float*)d_in[13];
    const float* W2    = (const float*)d_in[14];
    const float* b2    = (const float*)d_in[15];
    const float* lnfs  = (const float*)d_in[16];
    const float* lnfb  = (const float*)d_in[17];
    float* out = (float*)d_out;

    float *x, *h, *q, *k, *v, *o, *att, *ff;
    cudaGetSymbolAddress((void**)&x,   g_x);
    cudaGetSymbolAddress((void**)&h,   g_h);
    cudaGetSymbolAddress((void**)&q,   g_q);
    cudaGetSymbolAddress((void**)&k,   g_k);
    cudaGetSymbolAddress((void**)&v,   g_v);
    cudaGetSymbolAddress((void**)&o,   g_o);
    cudaGetSymbolAddress((void**)&att, g_att);
    cudaGetSymbolAddress((void**)&ff,  g_ff);

    embed_kernel<<<(NTOK * DD + 255) / 256, 256>>>(ids, emb, pe, x);

    const float scale = 0.125f;  // 1/sqrt(64)

    for (int l = 0; l < LL; l++) {
        ln_kernel<<<NTOK, 256>>>(x, ln1s + l * DD, ln1b + l * DD, h);

        gemm_kernel<0, false><<<dim3(NTOK / 128, DD / 128), 256>>>(
            h, Wq + (size_t)l * DD * DD, nullptr, nullptr, q, NTOK, DD, DD);
        gemm_kernel<0, false><<<dim3(NTOK / 128, DD / 128), 256>>>(
            h, Wk + (size_t)l * DD * DD, nullptr, nullptr, k, NTOK, DD, DD);
        gemm_kernel<0, false><<<dim3(NTOK / 128, DD / 128), 256>>>(
            h, Wv + (size_t)l * DD * DD, nullptr, nullptr, v, NTOK, DD, DD);

        attn_scores_kernel<<<dim3(SS / 64, SS / 64, BB * HH), 256>>>(q, k, att, scale);
        softmax_kernel<<<BB * HH * SS, 128>>>(att);
        attn_av_kernel<<<dim3(SS / 64, 1, BB * HH), 256>>>(att, v, o);

        gemm_kernel<2, false><<<dim3(NTOK / 128, DD / 128), 256>>>(
            o, Wo + (size_t)l * DD * DD, bo + l * DD, x, x, NTOK, DD, DD);

        ln_kernel<<<NTOK, 256>>>(x, ln2s + l * DD, ln2b + l * DD, h);

        gemm_kernel<1, false><<<dim3(NTOK / 128, FFD / 128), 256>>>(
            h, W1 + (size_t)l * DD * FFD, b1 + (size_t)l * FFD, nullptr, ff, NTOK, FFD, DD);

        gemm_kernel<2, false><<<dim3(NTOK / 128, DD / 128), 256>>>(
            ff, W2 + (size_t)l * FFD * DD, b2 + l * DD, x, x, NTOK, DD, FFD);
    }

    ln_kernel<<<NTOK, 256>>>(x, lnfs, lnfb, h);

    gemm_kernel<0, true><<<dim3(NTOK / 128, VV / 128), 256>>>(
        h, emb, nullptr, nullptr, out, NTOK, VV, DD);
}

// round 6
// speedup vs baseline: 1.8790x; 1.8790x over previous
#include <cuda_runtime.h>
#include <cuda_bf16.h>
#include <math.h>
#include <stdint.h>

// Problem constants
#define BB 4
#define SS 512
#define DD 1024
#define HH 16
#define LL 6
#define FFD 4096
#define VV 32000
#define DKK 64
#define NTOK (BB*SS)          // 2048

// ---------------------------------------------------------------------------
// Portable PTX helpers (no sm_103a-specific features!)
// ---------------------------------------------------------------------------
__device__ __forceinline__ uint32_t smem_to_u32(const void* smem_ptr) {
    uint32_t addr;
    asm("{ .reg .u64 tmp; cvta.to.shared.u64 tmp, %1; cvt.u32.u64 %0, tmp; }"
        : "=r"(addr) : "l"(smem_ptr));
    return addr;
}

__device__ __forceinline__ void cp_async16(uint32_t saddr, const void* gptr) {
    asm volatile("cp.async.cg.shared.global [%0], [%1], 16;"
                 :: "r"(saddr), "l"(gptr));
}
__device__ __forceinline__ void cp_commit() {
    asm volatile("cp.async.commit_group;" ::: "memory");
}
template <int N>
__device__ __forceinline__ void cp_wait() {
    asm volatile("cp.async.wait_group %0;" :: "n"(N) : "memory");
}

__device__ __forceinline__ void ldsm4(uint32_t* r, uint32_t addr) {
    asm volatile("ldmatrix.sync.aligned.m8n8.x4.shared.b16 {%0,%1,%2,%3}, [%4];"
        : "=r"(r[0]), "=r"(r[1]), "=r"(r[2]), "=r"(r[3]) : "r"(addr));
}

__device__ __forceinline__ void mma16816(float* c, const uint32_t* a, const uint32_t* b) {
    asm volatile(
        "mma.sync.aligned.m16n8k16.row.col.f32.bf16.bf16.f32 "
        "{%0,%1,%2,%3}, {%4,%5,%6,%7}, {%8,%9}, {%0,%1,%2,%3};"
        : "+f"(c[0]), "+f"(c[1]), "+f"(c[2]), "+f"(c[3])
        : "r"(a[0]), "r"(a[1]), "r"(a[2]), "r"(a[3]), "r"(b[0]), "r"(b[1]));
}

// ---------------------------------------------------------------------------
// Scratch (device globals; no allocation allowed)
// ---------------------------------------------------------------------------
__device__ float g_x[NTOK*DD];
__device__ float g_q[NTOK*DD];
__device__ float g_k[NTOK*DD];
__device__ float g_v[NTOK*DD];
__device__ float g_o[NTOK*DD];
__device__ float g_att[(size_t)BB*HH*SS*SS];   // 64 MB
__device__ float g_ff[(size_t)NTOK*FFD];       // 32 MB
__device__ __align__(16) __nv_bfloat16 g_ah[(size_t)NTOK*FFD];  // A hi
__device__ __align__(16) __nv_bfloat16 g_al[(size_t)NTOK*FFD];  // A lo
__device__ __align__(16) __nv_bfloat16 g_bh[(size_t)VV*DD];     // B hi
__device__ __align__(16) __nv_bfloat16 g_bl[(size_t)VV*DD];     // B lo

// ---------------------------------------------------------------------------
// Embedding + positional add (pe row indexed by BATCH index, per reference)
// ---------------------------------------------------------------------------
__global__ void embed_kernel(const int* __restrict__ ids,
                             const float* __restrict__ emb,
                             const float* __restrict__ pe,
                             float* __restrict__ x)
{
    int idx = blockIdx.x * blockDim.x + threadIdx.x;
    if (idx >= NTOK * DD) return;
    int row = idx / DD;
    int d   = idx - row * DD;
    int b   = row / SS;
    x[idx] = emb[(size_t)ids[row] * DD + d] + pe[b * DD + d];
}

// ---------------------------------------------------------------------------
// LayerNorm fused with fp32->bf16 hi/lo split
// ---------------------------------------------------------------------------
__global__ void ln_split_kernel(const float* __restrict__ x,
                                const float* __restrict__ s,
                                const float* __restrict__ bvec,
                                __nv_bfloat16* __restrict__ hi,
                                __nv_bfloat16* __restrict__ lo)
{
    __shared__ float red[256];
    int row = blockIdx.x;
    const float* p = x + (size_t)row * DD;
    int t = threadIdx.x;

    float acc = 0.f;
    for (int d = t; d < DD; d += 256) acc += p[d];
    red[t] = acc; __syncthreads();
    for (int o = 128; o > 0; o >>= 1) { if (t < o) red[t] += red[t + o]; __syncthreads(); }
    float mean = red[0] / DD;
    __syncthreads();

    acc = 0.f;
    for (int d = t; d < DD; d += 256) { float v = p[d] - mean; acc += v * v; }
    red[t] = acc; __syncthreads();
    for (int o = 128; o > 0; o >>= 1) { if (t < o) red[t] += red[t + o]; __syncthreads(); }
    float rstd = rsqrtf(red[0] / DD + 1e-5f);

    __nv_bfloat16* ph = hi + (size_t)row * DD;
    __nv_bfloat16* pl = lo + (size_t)row * DD;
    for (int d = t; d < DD; d += 256) {
        float v = (p[d] - mean) * rstd * s[d] + bvec[d];
        __nv_bfloat16 hh = __float2bfloat16(v);
        ph[d] = hh;
        pl[d] = __float2bfloat16(v - __bfloat162float(hh));
    }
}

// ---------------------------------------------------------------------------
// fp32 -> bf16 (hi, lo) elementwise split
// ---------------------------------------------------------------------------
__global__ void split_kernel(const float* __restrict__ x,
                             __nv_bfloat16* __restrict__ hi,
                             __nv_bfloat16* __restrict__ lo,
                             int n)
{
    int idx = blockIdx.x * blockDim.x + threadIdx.x;
    if (idx >= n) return;
    float v = x[idx];
    __nv_bfloat16 h = __float2bfloat16(v);
    float r = v - __bfloat162float(h);
    hi[idx] = h;
    lo[idx] = __float2bfloat16(r);
}

// ---------------------------------------------------------------------------
// fp32 W[K,N] -> bf16 hi/lo [N,K] (transpose + split)
// ---------------------------------------------------------------------------
__global__ void transpose_split_kernel(const float* __restrict__ W,
                                       __nv_bfloat16* __restrict__ bh,
                                       __nv_bfloat16* __restrict__ bl,
                                       int K, int N)
{
    __shared__ float ts[32][33];
    int k0 = blockIdx.y * 32, n0 = blockIdx.x * 32;
    int tx = threadIdx.x, ty = threadIdx.y;
#pragma unroll
    for (int i = 0; i < 4; i++)
        ts[ty + i * 8][tx] = W[(size_t)(k0 + ty + i * 8) * N + n0 + tx];
    __syncthreads();
#pragma unroll
    for (int i = 0; i < 4; i++) {
        float v = ts[tx][ty + i * 8];
        __nv_bfloat16 h = __float2bfloat16(v);
        float r = v - __bfloat162float(h);
        size_t o = (size_t)(n0 + ty + i * 8) * K + k0 + tx;
        bh[o] = h;
        bl[o] = __float2bfloat16(r);
    }
}

// ---------------------------------------------------------------------------
// mma.sync bf16x3 GEMM: C[M,N] = epi(sum_k A[m,k]*B[n,k] + bias) (+ res)
// A = (Ah, Al) [M,K] bf16 row-major; B = (Bh, Bl) [N,K] bf16 row-major.
// Tile 128x128x32, 256 threads (8 warps, 2x4 warp grid, 64x32 per warp),
// 3-stage cp.async pipeline, ldmatrix fragments, fp32 accum in registers.
// Requires M%128==0, N%128==0, K%32==0.
// OP: 0 none, 1 exact gelu, 2 add residual.
// ---------------------------------------------------------------------------
#define RS 40                 // smem row stride in bf16 elements (80 bytes)
#define TILE_B (128 * RS * 2) // 10240 bytes per tile
#define STAGE_B (4 * TILE_B)  // Ah, Al, Bh, Bl -> 40960 bytes
#define NSTAGE 3
#define MMA_SMEM (NSTAGE * STAGE_B)   // 122880

template <int OP>
__global__ __launch_bounds__(256, 1)
void gemm_mma_kernel(const __nv_bfloat16* __restrict__ Ah,
                     const __nv_bfloat16* __restrict__ Al,
                     const __nv_bfloat16* __restrict__ Bh,
                     const __nv_bfloat16* __restrict__ Bl,
                     const float* __restrict__ bias,
                     const float* __restrict__ res,
                     float* __restrict__ C,
                     int M, int N, int K)
{
    extern __shared__ char smem[];
    const uint32_t sbase = smem_to_u32(smem);
    const int tid  = threadIdx.x;
    const int lane = tid & 31;
    const int wid  = tid >> 5;
    const int wm   = wid >> 2;        // 0..1
    const int wn   = wid & 3;         // 0..3
    const int mTile = blockIdx.x * 128;
    const int nTile = blockIdx.y * 128;

    // global loader coords: per tile, 512 chunks of 16B; 2 per thread
    const int lrow0 = tid >> 1;            // pattern A: u = tid*? use u = tid + j*256
    (void)lrow0;

    // ldmatrix per-lane offsets
    const int aRow  = wm * 64 + (lane & 15);          // + fi*16
    const int aKoff = (lane >> 4) << 3;
    const int bRow  = wn * 32 + ((lane >> 4) << 3) + (lane & 7);  // + c*16
    const int bKoff = ((lane >> 3) & 1) << 3;

    float acc[4][4][4];
#pragma unroll
    for (int i = 0; i < 4; i++)
#pragma unroll
        for (int j = 0; j < 4; j++)
#pragma unroll
            for (int r = 0; r < 4; r++) acc[i][j][r] = 0.f;

    const int nst = K >> 5;

    // stage loader: tile t in {Ah, Al, Bh, Bl}
    auto load_stage = [&](int s) {
        uint32_t sb = sbase + (uint32_t)(s % NSTAGE) * STAGE_B;
        int kt = s << 5;
#pragma unroll
        for (int j = 0; j < 2; j++) {
            int u = tid + j * 256;         // 0..511
            int row = u >> 2, c = u & 3;   // c: 16B chunk (8 bf16)
            uint32_t so = (uint32_t)row * (RS * 2) + (uint32_t)c * 16;
            size_t ao = (size_t)(mTile + row) * K + kt + c * 8;
            size_t bo = (size_t)(nTile + row) * K + kt + c * 8;
            cp_async16(sb + so,              Ah + ao);
            cp_async16(sb + TILE_B + so,     Al + ao);
            cp_async16(sb + 2 * TILE_B + so, Bh + bo);
            cp_async16(sb + 3 * TILE_B + so, Bl + bo);
        }
        cp_commit();
    };

    load_stage(0);
    if (nst > 1) load_stage(1);

    for (int s = 0; s < nst; s++) {
        __syncthreads();   // all warps done computing stage s-1 before its buffer is reloaded
        if (s + 2 < nst) load_stage(s + 2);
        int ng = nst - 1 - s; if (ng > 2) ng = 2;
        if (ng == 2)      cp_wait<2>();
        else if (ng == 1) cp_wait<1>();
        else              cp_wait<0>();
        __syncthreads();

        uint32_t sb  = sbase + (uint32_t)(s % NSTAGE) * STAGE_B;
        uint32_t sAh = sb;
        uint32_t sAl = sb + TILE_B;
        uint32_t sBh = sb + 2 * TILE_B;
        uint32_t sBl = sb + 3 * TILE_B;

#pragma unroll
        for (int kk = 0; kk < 32; kk += 16) {
            uint32_t a[4][4], bh4[2][4], bl4[2][4];
            // A-hi fragments
#pragma unroll
            for (int fi = 0; fi < 4; fi++)
                ldsm4(a[fi], sAh + (uint32_t)(aRow + fi * 16) * (RS * 2)
                                 + (uint32_t)(kk + aKoff) * 2);
            // B-hi fragments (two x4 loads cover 4 n8 frags)
#pragma unroll
            for (int c = 0; c < 2; c++)
                ldsm4(bh4[c], sBh + (uint32_t)(bRow + c * 16) * (RS * 2)
                                  + (uint32_t)(kk + bKoff) * 2);
            // pass 1: Ah x Bh
#pragma unroll
            for (int fi = 0; fi < 4; fi++)
#pragma unroll
                for (int fj = 0; fj < 4; fj++)
                    mma16816(acc[fi][fj], a[fi], &bh4[fj >> 1][(fj & 1) * 2]);
            // B-lo fragments
#pragma unroll
            for (int c = 0; c < 2; c++)
                ldsm4(bl4[c], sBl + (uint32_t)(bRow + c * 16) * (RS * 2)
                                  + (uint32_t)(kk + bKoff) * 2);
            // pass 2: Ah x Bl
#pragma unroll
            for (int fi = 0; fi < 4; fi++)
#pragma unroll
                for (int fj = 0; fj < 4; fj++)
                    mma16816(acc[fi][fj], a[fi], &bl4[fj >> 1][(fj & 1) * 2]);
            // A-lo fragments (overwrite a)
#pragma unroll
            for (int fi = 0; fi < 4; fi++)
                ldsm4(a[fi], sAl + (uint32_t)(aRow + fi * 16) * (RS * 2)
                                 + (uint32_t)(kk + aKoff) * 2);
            // pass 3: Al x Bh
#pragma unroll
            for (int fi = 0; fi < 4; fi++)
#pragma unroll
                for (int fj = 0; fj < 4; fj++)
                    mma16816(acc[fi][fj], a[fi], &bh4[fj >> 1][(fj & 1) * 2]);
        }
    }

    // epilogue: c0,c1 -> (r, c..c+1); c2,c3 -> (r+8, c..c+1)
#pragma unroll
    for (int fi = 0; fi < 4; fi++) {
        int r0 = mTile + wm * 64 + fi * 16 + (lane >> 2);
#pragma unroll
        for (int fj = 0; fj < 4; fj++) {
            int cc = nTile + wn * 32 + fj * 8 + (lane & 3) * 2;
            float b0 = 0.f, b1 = 0.f;
            if (bias) { b0 = bias[cc]; b1 = bias[cc + 1]; }
#pragma unroll
            for (int half = 0; half < 2; half++) {
                int r = r0 + half * 8;
                float v0 = acc[fi][fj][half * 2 + 0] + b0;
                float v1 = acc[fi][fj][half * 2 + 1] + b1;
                if (OP == 1) {
                    v0 = 0.5f * v0 * (1.0f + erff(v0 * 0.70710678118654752f));
                    v1 = 0.5f * v1 * (1.0f + erff(v1 * 0.70710678118654752f));
                }
                size_t ci = (size_t)r * N + cc;
                if (OP == 2) {
                    float2 rr = *(const float2*)(res + ci);
                    v0 += rr.x; v1 += rr.y;
                }
                float2 ov = {v0, v1};
                *(float2*)(C + ci) = ov;
            }
        }
    }
}

// ---------------------------------------------------------------------------
// Attention: scores = scale * Q Kt (causal), per (b,h). 64x64 tiles, DK=64.
// ---------------------------------------------------------------------------
__global__ void attn_scores_kernel(const float* __restrict__ q,
                                   const float* __restrict__ k,
                                   float* __restrict__ att,
                                   float scale)
{
    if (blockIdx.x > blockIdx.y) return;   // fully masked tile
    __shared__ float As[16][65];
    __shared__ float Bs[16][65];

    int bh = blockIdx.z;
    int b = bh / HH, h = bh % HH;
    int qi0 = blockIdx.y * 64, ki0 = blockIdx.x * 64;
    int tid = threadIdx.x;

    const float* qb = q + (size_t)b * SS * DD + h * DKK;
    const float* kb = k + (size_t)b * SS * DD + h * DKK;

    int m0 = (tid >> 4) * 4;
    int n0 = (tid & 15) * 4;

    float acc[4][4];
#pragma unroll
    for (int i = 0; i < 4; i++)
#pragma unroll
        for (int j = 0; j < 4; j++) acc[i][j] = 0.f;

    for (int kt = 0; kt < DKK; kt += 16) {
#pragma unroll
        for (int i = 0; i < 4; i++) {
            int e = tid + i * 256;
            int m = e >> 4, kk = e & 15;
            As[kk][m] = qb[(size_t)(qi0 + m) * DD + kt + kk];
            Bs[kk][m] = kb[(size_t)(ki0 + m) * DD + kt + kk];
        }
        __syncthreads();
#pragma unroll
        for (int kk = 0; kk < 16; kk++) {
            float a[4], bbv[4];
#pragma unroll
            for (int i = 0; i < 4; i++) a[i] = As[kk][m0 + i];
#pragma unroll
            for (int j = 0; j < 4; j++) bbv[j] = Bs[kk][n0 + j];
#pragma unroll
            for (int i = 0; i < 4; i++)
#pragma unroll
                for (int j = 0; j < 4; j++) acc[i][j] = fmaf(a[i], bbv[j], acc[i][j]);
        }
        __syncthreads();
    }

#pragma unroll
    for (int i = 0; i < 4; i++) {
        int qi = qi0 + m0 + i;
#pragma unroll
        for (int j = 0; j < 4; j++) {
            int ki = ki0 + n0 + j;
            float v = acc[i][j] * scale;
            if (ki > qi) v = -1e30f;
            att[((size_t)bh * SS + qi) * SS + ki] = v;
        }
    }
}

// ---------------------------------------------------------------------------
// Causal softmax over a row (length qi+1); zeros the masked tail.
// ---------------------------------------------------------------------------
__global__ void softmax_kernel(float* __restrict__ att)
{
    __shared__ float red[128];
    int r = blockIdx.x;
    int qi = r & (SS - 1);
    float* p = att + (size_t)r * SS;
    int len = qi + 1;
    int t = threadIdx.x;

    float mx = -1e30f;
    for (int i = t; i < len; i += 128) mx = fmaxf(mx, p[i]);
    red[t] = mx; __syncthreads();
    for (int o = 64; o > 0; o >>= 1) { if (t < o) red[t] = fmaxf(red[t], red[t + o]); __syncthreads(); }
    mx = red[0]; __syncthreads();

    float sm = 0.f;
    for (int i = t; i < len; i += 128) sm += expf(p[i] - mx);
    red[t] = sm; __syncthreads();
    for (int o = 64; o > 0; o >>= 1) { if (t < o) red[t] += red[t + o]; __syncthreads(); }
    float inv = 1.0f / red[0];

    for (int i = t; i < len; i += 128) p[i] = expf(p[i] - mx) * inv;
    for (int i = len + t; i < SS; i += 128) p[i] = 0.f;
}

// ---------------------------------------------------------------------------
// O = att @ V per (b,h). Tile 64(qi) x 64(d); K limited causally to the tile.
// ---------------------------------------------------------------------------
__global__ void attn_av_kernel(const float* __restrict__ att,
                               const float* __restrict__ v,
                               float* __restrict__ o)
{
    __shared__ float As[16][65];
    __shared__ float Bs[16][65];

    int bh = blockIdx.z;
    int b = bh / HH, h = bh % HH;
    int qi0 = blockIdx.x * 64;
    int tid = threadIdx.x;

    const float* ab = att + (size_t)bh * SS * SS;
    const float* vb = v + (size_t)b * SS * DD + h * DKK;

    int m0 = (tid >> 4) * 4;
    int n0 = (tid & 15) * 4;

    float acc[4][4];
#pragma unroll
    for (int i = 0; i < 4; i++)
#pragma unroll
        for (int j = 0; j < 4; j++) acc[i][j] = 0.f;

    int kmax = qi0 + 64;
    for (int kt = 0; kt < kmax; kt += 16) {
#pragma unroll
        for (int i = 0; i < 4; i++) {
            int e = tid + i * 256;
            { int m = e >> 4, kk = e & 15;
              As[kk][m] = ab[(size_t)(qi0 + m) * SS + kt + kk]; }
            { int kk = e >> 6, n = e & 63;
              Bs[kk][n] = vb[(size_t)(kt + kk) * DD + n]; }
        }
        __syncthreads();
#pragma unroll
        for (int kk = 0; kk < 16; kk++) {
            float a[4], bbv[4];
#pragma unroll
            for (int i = 0; i < 4; i++) a[i] = As[kk][m0 + i];
#pragma unroll
            for (int j = 0; j < 4; j++) bbv[j] = Bs[kk][n0 + j];
#pragma unroll
            for (int i = 0; i < 4; i++)
#pragma unroll
                for (int j = 0; j < 4; j++) acc[i][j] = fmaf(a[i], bbv[j], acc[i][j]);
        }
        __syncthreads();
    }

#pragma unroll
    for (int i = 0; i < 4; i++) {
        int qi = qi0 + m0 + i;
#pragma unroll
        for (int j = 0; j < 4; j++)
            o[((size_t)b * SS + qi) * DD + h * DKK + n0 + j] = acc[i][j];
    }
}

// ---------------------------------------------------------------------------
// Host launcher
// ---------------------------------------------------------------------------
extern "C" void kernel_launch(void* const* d_in, const int* in_sizes, int n_in,
                              void* d_out, int out_size)
{
    const int*   ids   = (const int*)  d_in[0];
    const float* emb   = (const float*)d_in[1];
    const float* pe    = (const float*)d_in[2];
    const float* Wq    = (const float*)d_in[3];
    const float* Wk    = (const float*)d_in[4];
    const float* Wv    = (const float*)d_in[5];
    const float* Wo    = (const float*)d_in[6];
    const float* bo    = (const float*)d_in[7];
    const float* ln1s  = (const float*)d_in[8];
    const float* ln1b  = (const float*)d_in[9];
    const float* ln2s  = (const float*)d_in[10];
    const float* ln2b  = (const float*)d_in[11];
    const float* W1    = (const float*)d_in[12];
    const float* b1    = (const float*)d_in[13];
    const float* W2    = (const float*)d_in[14];
    const float* b2    = (const float*)d_in[15];
    const float* lnfs  = (const float*)d_in[16];
    const float* lnfb  = (const float*)d_in[17];
    float* out = (float*)d_out;

    float *x, *q, *k, *v, *o, *att, *ff;
    __nv_bfloat16 *ah, *al, *bh, *bl;
    cudaGetSymbolAddress((void**)&x,   g_x);
    cudaGetSymbolAddress((void**)&q,   g_q);
    cudaGetSymbolAddress((void**)&k,   g_k);
    cudaGetSymbolAddress((void**)&v,   g_v);
    cudaGetSymbolAddress((void**)&o,   g_o);
    cudaGetSymbolAddress((void**)&att, g_att);
    cudaGetSymbolAddress((void**)&ff,  g_ff);
    cudaGetSymbolAddress((void**)&ah,  g_ah);
    cudaGetSymbolAddress((void**)&al,  g_al);
    cudaGetSymbolAddress((void**)&bh,  g_bh);
    cudaGetSymbolAddress((void**)&bl,  g_bl);

    cudaFuncSetAttribute(gemm_mma_kernel<0>, cudaFuncAttributeMaxDynamicSharedMemorySize, MMA_SMEM);
    cudaFuncSetAttribute(gemm_mma_kernel<1>, cudaFuncAttributeMaxDynamicSharedMemorySize, MMA_SMEM);
    cudaFuncSetAttribute(gemm_mma_kernel<2>, cudaFuncAttributeMaxDynamicSharedMemorySize, MMA_SMEM);

    embed_kernel<<<(NTOK * DD + 255) / 256, 256>>>(ids, emb, pe, x);

    const float scale = 0.125f;  // 1/sqrt(64)
    dim3 tblk(32, 8);

    for (int l = 0; l < LL; l++) {
        ln_split_kernel<<<NTOK, 256>>>(x, ln1s + l * DD, ln1b + l * DD, ah, al);

        // QKV
        transpose_split_kernel<<<dim3(DD / 32, DD / 32), tblk>>>(Wq + (size_t)l * DD * DD, bh, bl, DD, DD);
        gemm_mma_kernel<0><<<dim3(NTOK / 128, DD / 128), 256, MMA_SMEM>>>(
            ah, al, bh, bl, nullptr, nullptr, q, NTOK, DD, DD);
        transpose_split_kernel<<<dim3(DD / 32, DD / 32), tblk>>>(Wk + (size_t)l * DD * DD, bh, bl, DD, DD);
        gemm_mma_kernel<0><<<dim3(NTOK / 128, DD / 128), 256, MMA_SMEM>>>(
            ah, al, bh, bl, nullptr, nullptr, k, NTOK, DD, DD);
        transpose_split_kernel<<<dim3(DD / 32, DD / 32), tblk>>>(Wv + (size_t)l * DD * DD, bh, bl, DD, DD);
        gemm_mma_kernel<0><<<dim3(NTOK / 128, DD / 128), 256, MMA_SMEM>>>(
            ah, al, bh, bl, nullptr, nullptr, v, NTOK, DD, DD);

        attn_scores_kernel<<<dim3(SS / 64, SS / 64, BB * HH), 256>>>(q, k, att, scale);
        softmax_kernel<<<BB * HH * SS, 128>>>(att);
        attn_av_kernel<<<dim3(SS / 64, 1, BB * HH), 256>>>(att, v, o);

        // x = x + o @ Wo + bo
        split_kernel<<<(NTOK * DD + 255) / 256, 256>>>(o, ah, al, NTOK * DD);
        transpose_split_kernel<<<dim3(DD / 32, DD / 32), tblk>>>(Wo + (size_t)l * DD * DD, bh, bl, DD, DD);
        gemm_mma_kernel<2><<<dim3(NTOK / 128, DD / 128), 256, MMA_SMEM>>>(
            ah, al, bh, bl, bo + l * DD, x, x, NTOK, DD, DD);

        // FFN
        ln_split_kernel<<<NTOK, 256>>>(x, ln2s + l * DD, ln2b + l * DD, ah, al);
        transpose_split_kernel<<<dim3(FFD / 32, DD / 32), tblk>>>(W1 + (size_t)l * DD * FFD, bh, bl, DD, FFD);
        gemm_mma_kernel<1><<<dim3(NTOK / 128, FFD / 128), 256, MMA_SMEM>>>(
            ah, al, bh, bl, b1 + (size_t)l * FFD, nullptr, ff, NTOK, FFD, DD);

        split_kernel<<<(NTOK * FFD + 255) / 256, 256>>>(ff, ah, al, NTOK * FFD);
        transpose_split_kernel<<<dim3(DD / 32, FFD / 32), tblk>>>(W2 + (size_t)l * FFD * DD, bh, bl, FFD, DD);
        gemm_mma_kernel<2><<<dim3(NTOK / 128, DD / 128), 256, MMA_SMEM>>>(
            ah, al, bh, bl, b2 + l * DD, x, x, NTOK, DD, FFD);
    }

    ln_split_kernel<<<NTOK, 256>>>(x, lnfs, lnfb, ah, al);
    // lm-head: emb is [V, D] = [N, K] row-major already (NT) — split only
    split_kernel<<<(VV * DD + 255) / 256, 256>>>(emb, bh, bl, VV * DD);
    gemm_mma_kernel<0><<<dim3(NTOK / 128, VV / 128), 256, MMA_SMEM>>>(
        ah, al, bh, bl, nullptr, nullptr, out, NTOK, VV, DD);
}